// round 16
// baseline (speedup 1.0000x reference)
#include <cuda_runtime.h>
#include <cuda_bf16.h>
#include <math.h>

#define NN 4096
#define DD 512
#define CC 128
#define ALPHA_ 0.0005f
#define NT 32
#define NBLK_DIST (NT * (NT + 1) / 2)   // 528
#define KEY_EMPTY __uint_as_float(0x7f7fffffu)

typedef unsigned long long ull;

__device__ float g_sq[NN];
__device__ float g_part[NN * NT * 3];
__device__ float g_loss;
__device__ float g_reg;
__device__ unsigned g_done;
__device__ float g_logits[NN * CC];
__device__ __nv_bfloat16 g_xhi[NN * DD];
__device__ __nv_bfloat16 g_xlo[NN * DD];
__device__ __nv_bfloat16 g_wt_hi[CC * DD];
__device__ __nv_bfloat16 g_wt_lo[CC * DD];

__device__ __forceinline__ void ins3f(float &a0, float &a1, float &a2, float k) {
    a2 = fminf(a2, k);
    float lo = fminf(a1, a2), hi = fmaxf(a1, a2);
    a1 = lo; a2 = hi;
    lo = fminf(a0, a1); hi = fmaxf(a0, a1);
    a0 = lo; a1 = hi;
}

__device__ __forceinline__ float packkey(float e2, unsigned idx) {
    return __uint_as_float((__float_as_uint(e2) & 0xFFFFF000u) | idx);
}

__device__ __forceinline__ unsigned smem_u32(const void* p) {
    unsigned a;
    asm("{ .reg .u64 t; cvta.to.shared.u64 t, %1; cvt.u32.u64 %0, t; }" : "=r"(a) : "l"(p));
    return a;
}

#define LDSMX4(r0, r1, r2, r3, addr) \
    asm volatile("ldmatrix.sync.aligned.m8n8.x4.shared.b16 {%0,%1,%2,%3}, [%4];" \
        : "=r"(r0), "=r"(r1), "=r"(r2), "=r"(r3) : "r"(addr))

#define MMA16816(d, a, b) \
    asm volatile("mma.sync.aligned.m16n8k16.row.col.f32.bf16.bf16.f32 " \
        "{%0,%1,%2,%3}, {%4,%5,%6,%7}, {%8,%9}, {%0,%1,%2,%3};" \
        : "+f"((d)[0]), "+f"((d)[1]), "+f"((d)[2]), "+f"((d)[3]) \
        : "r"((a)[0]), "r"((a)[1]), "r"((a)[2]), "r"((a)[3]), "r"((b)[0]), "r"((b)[1]))

// fused: bf16 hi/lo split + sq-norms (blocks 0..511) AND W^T prep + logits zero + init (blocks 512..767)
__global__ void k_cvt_sq(const float* __restrict__ x, const float* __restrict__ W) {
    if (blockIdx.x >= 512) {
        int idx = (blockIdx.x - 512) * 256 + threadIdx.x;   // 0..65535
        if (idx == 0) { g_loss = 0.f; g_reg = 0.f; g_done = 0u; }
        int c = idx >> 9, d = idx & 511;
        float v = W[d * CC + c];
        __nv_bfloat16 h = __float2bfloat16(v);
        __nv_bfloat16 l = __float2bfloat16(v - __bfloat162float(h));
        g_wt_hi[c * DD + d] = h;
        g_wt_lo[c * DD + d] = l;
        float4 z = make_float4(0.f, 0.f, 0.f, 0.f);
        ((float4*)g_logits)[idx] = z;
        ((float4*)g_logits)[idx + 65536] = z;
        return;
    }
    int row  = (blockIdx.x * blockDim.x + threadIdx.x) >> 5;
    int lane = threadIdx.x & 31;
    float s = 0.f;
    #pragma unroll
    for (int q = 0; q < 4; ++q) {
        size_t i = (size_t)row * DD + lane * 4 + q * 128;
        float4 v = *(const float4*)(x + i);
        s = fmaf(v.x, v.x, s); s = fmaf(v.y, v.y, s);
        s = fmaf(v.z, v.z, s); s = fmaf(v.w, v.w, s);
        __nv_bfloat16 h0 = __float2bfloat16(v.x), h1 = __float2bfloat16(v.y);
        __nv_bfloat16 h2 = __float2bfloat16(v.z), h3 = __float2bfloat16(v.w);
        __nv_bfloat16 l0 = __float2bfloat16(v.x - __bfloat162float(h0));
        __nv_bfloat16 l1 = __float2bfloat16(v.y - __bfloat162float(h1));
        __nv_bfloat16 l2 = __float2bfloat16(v.z - __bfloat162float(h2));
        __nv_bfloat16 l3 = __float2bfloat16(v.w - __bfloat162float(h3));
        __nv_bfloat162 hA; hA.x = h0; hA.y = h1;
        __nv_bfloat162 hB; hB.x = h2; hB.y = h3;
        __nv_bfloat162 lA; lA.x = l0; lA.y = l1;
        __nv_bfloat162 lB; lB.x = l2; lB.y = l3;
        *(__nv_bfloat162*)(g_xhi + i)     = hA;
        *(__nv_bfloat162*)(g_xhi + i + 2) = hB;
        *(__nv_bfloat162*)(g_xlo + i)     = lA;
        *(__nv_bfloat162*)(g_xlo + i + 2) = lB;
    }
    #pragma unroll
    for (int off = 16; off; off >>= 1) s += __shfl_down_sync(0xffffffffu, s, off);
    if (lane == 0) g_sq[row] = s;
}

// ---- loss-GEMM path (blocks >= NBLK_DIST of the fused kernel) ----
__device__ void loss_mma_body(char* dsm, int bid) {
    const unsigned TILESZ = 18432;
    int t = threadIdx.x, lane = t & 31, wid = t >> 5;
    int wm = wid >> 1, wn = wid & 1;
    int mbase = wm * 32, nbase = wn * 64;

    int rg = bid >> 2;
    int ks = bid & 3;
    int rowA = rg * 128;
    int dbase = ks * 128;

    unsigned sb = smem_u32(dsm);
    unsigned aOff = (mbase + (lane & 15)) * 144 + (lane >> 4) * 16;
    unsigned bOff = (nbase + (lane & 7) + ((lane >> 4) << 3)) * 144 + ((lane >> 3) & 1) * 16;

    float acc[2][8][4];
    #pragma unroll
    for (int i = 0; i < 2; i++)
        #pragma unroll
        for (int j = 0; j < 8; j++)
            #pragma unroll
            for (int k = 0; k < 4; k++) acc[i][j][k] = 0.f;

    for (int chunk = 0; chunk < 2; ++chunk) {
        int d0 = dbase + chunk * 64;
        __syncthreads();
        #pragma unroll
        for (int it = 0; it < 16; ++it) {
            int i = t + 256 * it;
            int tile = i >> 10, rem = i & 1023;
            int r = rem >> 3, q = rem & 7;
            const __nv_bfloat16* src;
            if      (tile == 0) src = g_xhi  + (size_t)(rowA + r) * DD + d0 + q * 8;
            else if (tile == 1) src = g_xlo  + (size_t)(rowA + r) * DD + d0 + q * 8;
            else if (tile == 2) src = g_wt_hi + (size_t)r * DD + d0 + q * 8;
            else                src = g_wt_lo + (size_t)r * DD + d0 + q * 8;
            *(float4*)(dsm + tile * TILESZ + r * 144 + q * 16) = *(const float4*)src;
        }
        __syncthreads();

        unsigned baseAh = sb, baseAl = sb + TILESZ, baseBh = sb + 2 * TILESZ, baseBl = sb + 3 * TILESZ;
        #pragma unroll
        for (int kh = 0; kh < 4; ++kh) {
            unsigned ko = kh * 32;
            unsigned aH[2][4], aL[2][4], bH[8][2], bL[8][2];
            LDSMX4(aH[0][0], aH[0][1], aH[0][2], aH[0][3], baseAh + aOff + ko);
            LDSMX4(aH[1][0], aH[1][1], aH[1][2], aH[1][3], baseAh + aOff + 16 * 144 + ko);
            LDSMX4(aL[0][0], aL[0][1], aL[0][2], aL[0][3], baseAl + aOff + ko);
            LDSMX4(aL[1][0], aL[1][1], aL[1][2], aL[1][3], baseAl + aOff + 16 * 144 + ko);
            #pragma unroll
            for (int g = 0; g < 4; ++g) {
                LDSMX4(bH[2*g][0], bH[2*g][1], bH[2*g+1][0], bH[2*g+1][1],
                       baseBh + bOff + g * 16 * 144 + ko);
                LDSMX4(bL[2*g][0], bL[2*g][1], bL[2*g+1][0], bL[2*g+1][1],
                       baseBl + bOff + g * 16 * 144 + ko);
            }
            #pragma unroll
            for (int mt = 0; mt < 2; ++mt)
                #pragma unroll
                for (int nt = 0; nt < 8; ++nt) {
                    MMA16816(acc[mt][nt], aH[mt], bH[nt]);
                    MMA16816(acc[mt][nt], aH[mt], bL[nt]);
                    MMA16816(acc[mt][nt], aL[mt], bH[nt]);
                }
        }
    }

    #pragma unroll
    for (int mt = 0; mt < 2; ++mt)
        #pragma unroll
        for (int nt = 0; nt < 8; ++nt)
            #pragma unroll
            for (int c4 = 0; c4 < 4; ++c4) {
                int h = c4 >> 1, c = c4 & 1;
                int ml = mbase + mt * 16 + (lane >> 2) + h * 8;
                int nl = nbase + nt * 8 + 2 * (lane & 3) + c;
                atomicAdd(&g_logits[(size_t)(rowA + ml) * CC + nl], acc[mt][nt][c4]);
            }
}

// ---- fused GEMM kernel: blocks [0,528) distance+top3, [528,656) loss logits ----
__global__ __launch_bounds__(256, 2) void k_gemm_fused() {
    extern __shared__ __align__(16) char dsm[];

    if (blockIdx.x >= NBLK_DIST) {
        loss_mma_body(dsm, blockIdx.x - NBLK_DIST);
        return;
    }

    float* s_sqA = (float*)dsm;
    float* s_sqB = (float*)(dsm + 512);
    const unsigned BUF0 = 1024, BUFSZ = 20480, TILESZ = 10240;

    int t = threadIdx.x, lane = t & 31, wid = t >> 5;
    int wm = wid >> 1, wn = wid & 1;
    int mbase = wm * 32, nbase = wn * 64;

    int id = blockIdx.x, by = 0;
    while (id >= NT - by) { id -= NT - by; by++; }
    int bx = by + id;
    int rowA = by * 128, rowB = bx * 128;

    if (t < 128) { s_sqA[t] = g_sq[rowA + t]; s_sqB[t] = g_sq[rowB + t]; }

    unsigned sb = smem_u32(dsm);

    const char* srcPtr[4];
    unsigned dstOff[4];
    #pragma unroll
    for (int c = 0; c < 4; ++c) {
        int tile = c & 1, part = c >> 1;
        int i2 = t + 256 * part;
        int r = i2 >> 2, q = i2 & 3;
        int rowT = tile ? rowB : rowA;
        srcPtr[c] = (const char*)g_xhi + ((size_t)(rowT + r) << 10) + q * 16;
        dstOff[c] = BUF0 + tile * TILESZ + r * 80 + q * 16;
    }

    float acc[2][8][4];
    #pragma unroll
    for (int i = 0; i < 2; i++)
        #pragma unroll
        for (int j = 0; j < 8; j++)
            #pragma unroll
            for (int k = 0; k < 4; k++) acc[i][j][k] = 0.f;

    unsigned aOff = ((mbase + (lane & 15)) * 40 + (lane >> 4) * 8) * 2;
    unsigned bOff = ((nbase + (lane & 7) + ((lane >> 4) << 3)) * 40 + ((lane >> 3) & 1) * 8) * 2;

    #pragma unroll
    for (int c = 0; c < 4; ++c)
        asm volatile("cp.async.cg.shared.global [%0], [%1], 16;"
            :: "r"(sb + dstOff[c]), "l"(srcPtr[c]) : "memory");
    asm volatile("cp.async.commit_group;" ::: "memory");
    #pragma unroll
    for (int c = 0; c < 4; ++c)
        asm volatile("cp.async.cg.shared.global [%0], [%1], 16;"
            :: "r"(sb + dstOff[c] + BUFSZ), "l"(srcPtr[c] + 64) : "memory");
    asm volatile("cp.async.commit_group;" ::: "memory");

    for (int s = 0; s < 16; ++s) {
        if (s < 15) asm volatile("cp.async.wait_group 1;" ::: "memory");
        else        asm volatile("cp.async.wait_group 0;" ::: "memory");
        __syncthreads();

        if (s + 2 < 16) {
            unsigned bofs = ((s + 2) % 3) * BUFSZ;
            #pragma unroll
            for (int c = 0; c < 4; ++c)
                asm volatile("cp.async.cg.shared.global [%0], [%1], 16;"
                    :: "r"(sb + dstOff[c] + bofs), "l"(srcPtr[c] + (size_t)(s + 2) * 64) : "memory");
            asm volatile("cp.async.commit_group;" ::: "memory");
        }

        unsigned bb = sb + BUF0 + (s % 3) * BUFSZ;
        unsigned baseA = bb, baseB = bb + TILESZ;

        #pragma unroll
        for (int kh = 0; kh < 2; ++kh) {
            unsigned ko = kh * 32;
            unsigned aH[2][4], bb2[8][2];
            LDSMX4(aH[0][0], aH[0][1], aH[0][2], aH[0][3], baseA + aOff + ko);
            LDSMX4(aH[1][0], aH[1][1], aH[1][2], aH[1][3], baseA + aOff + 16 * 80 + ko);
            #pragma unroll
            for (int g = 0; g < 4; ++g)
                LDSMX4(bb2[2*g][0], bb2[2*g][1], bb2[2*g+1][0], bb2[2*g+1][1],
                       baseB + bOff + g * 16 * 80 + ko);
            #pragma unroll
            for (int mt = 0; mt < 2; ++mt)
                #pragma unroll
                for (int nt = 0; nt < 8; ++nt)
                    MMA16816(acc[mt][nt], aH[mt], bb2[nt]);
        }
    }
    __syncthreads();

    const float* sqa = s_sqA;
    const float* sqb = s_sqB;
    #pragma unroll
    for (int mt = 0; mt < 2; ++mt)
        #pragma unroll
        for (int nt = 0; nt < 8; ++nt)
            #pragma unroll
            for (int c4 = 0; c4 < 4; ++c4) {
                int h = c4 >> 1, c = c4 & 1;
                int ml = mbase + mt * 16 + (lane >> 2) + h * 8;
                int nl = nbase + nt * 8 + 2 * (lane & 3) + c;
                float d2 = sqa[ml] + sqb[nl] - 2.f * acc[mt][nt][c4];
                float e2 = d2 > 0.f ? d2 : 0.f;
                if (rowA + ml == rowB + nl) e2 = 0.f;
                acc[mt][nt][c4] = e2;
            }

    float* p_r = (float*)(dsm + BUF0);
    float* p_c = (float*)(dsm + BUF0 + 4096);

    #pragma unroll
    for (int mt = 0; mt < 2; ++mt)
        #pragma unroll
        for (int h = 0; h < 2; ++h) {
            int ml = mbase + mt * 16 + (lane >> 2) + h * 8;
            float t0 = KEY_EMPTY, t1 = KEY_EMPTY, t2 = KEY_EMPTY;
            #pragma unroll
            for (int nt = 0; nt < 8; ++nt)
                #pragma unroll
                for (int c = 0; c < 2; ++c) {
                    int nl = nbase + nt * 8 + 2 * (lane & 3) + c;
                    ins3f(t0, t1, t2, packkey(acc[mt][nt][2 * h + c], (unsigned)(rowB + nl)));
                }
            #pragma unroll
            for (int off = 1; off <= 2; off <<= 1) {
                float r0 = __shfl_xor_sync(0xffffffffu, t0, off);
                float r1 = __shfl_xor_sync(0xffffffffu, t1, off);
                float r2 = __shfl_xor_sync(0xffffffffu, t2, off);
                ins3f(t0, t1, t2, r0); ins3f(t0, t1, t2, r1); ins3f(t0, t1, t2, r2);
            }
            if ((lane & 3) == 0) {
                int b = (ml * 2 + wn) * 3;
                p_r[b + 0] = t0; p_r[b + 1] = t1; p_r[b + 2] = t2;
            }
        }

    if (bx != by) {
        #pragma unroll
        for (int nt = 0; nt < 8; ++nt)
            #pragma unroll
            for (int c = 0; c < 2; ++c) {
                int nl = nbase + nt * 8 + 2 * (lane & 3) + c;
                float t0 = KEY_EMPTY, t1 = KEY_EMPTY, t2 = KEY_EMPTY;
                #pragma unroll
                for (int mt = 0; mt < 2; ++mt)
                    #pragma unroll
                    for (int h = 0; h < 2; ++h) {
                        int ml = mbase + mt * 16 + (lane >> 2) + h * 8;
                        ins3f(t0, t1, t2, packkey(acc[mt][nt][2 * h + c], (unsigned)(rowA + ml)));
                    }
                #pragma unroll
                for (int off = 4; off <= 16; off <<= 1) {
                    float r0 = __shfl_xor_sync(0xffffffffu, t0, off);
                    float r1 = __shfl_xor_sync(0xffffffffu, t1, off);
                    float r2 = __shfl_xor_sync(0xffffffffu, t2, off);
                    ins3f(t0, t1, t2, r0); ins3f(t0, t1, t2, r1); ins3f(t0, t1, t2, r2);
                }
                if (lane < 4) {
                    int b = (nl * 4 + wm) * 3;
                    p_c[b + 0] = t0; p_c[b + 1] = t1; p_c[b + 2] = t2;
                }
            }
    }

    __syncthreads();
    if (t < 128) {
        float t0 = KEY_EMPTY, t1 = KEY_EMPTY, t2 = KEY_EMPTY;
        #pragma unroll
        for (int g = 0; g < 6; ++g) ins3f(t0, t1, t2, p_r[t * 6 + g]);
        size_t base = ((size_t)(rowA + t) * NT + bx) * 3;
        g_part[base + 0] = t0; g_part[base + 1] = t1; g_part[base + 2] = t2;
    } else if (bx != by) {
        int n = t - 128;
        float t0 = KEY_EMPTY, t1 = KEY_EMPTY, t2 = KEY_EMPTY;
        #pragma unroll
        for (int g = 0; g < 12; ++g) ins3f(t0, t1, t2, p_c[n * 12 + g]);
        size_t base = ((size_t)(rowB + n) * NT + by) * 3;
        g_part[base + 0] = t0; g_part[base + 1] = t1; g_part[base + 2] = t2;
    }
}

// fused: softmax+NLL and merge+reg, warp per row; block-reduced atomics; last block writes out
__global__ void k_tail(const int* __restrict__ y, const float* __restrict__ yo,
                       const float* __restrict__ b, float* __restrict__ out) {
    __shared__ float s_loss[8];
    __shared__ float s_reg[8];
    int w    = threadIdx.x >> 5;
    int row  = blockIdx.x * 8 + w;
    int lane = threadIdx.x & 31;

    float l[4];
    #pragma unroll
    for (int q = 0; q < 4; ++q)
        l[q] = g_logits[(size_t)row * CC + lane + 32 * q] + b[lane + 32 * q];
    float t0 = KEY_EMPTY, t1 = KEY_EMPTY, t2 = KEY_EMPTY;
    size_t pbase = (size_t)row * (NT * 3);
    #pragma unroll
    for (int p = 0; p < 3; ++p) ins3f(t0, t1, t2, g_part[pbase + lane + 32 * p]);

    float mx = fmaxf(fmaxf(l[0], l[1]), fmaxf(l[2], l[3]));
    #pragma unroll
    for (int off = 16; off; off >>= 1) mx = fmaxf(mx, __shfl_xor_sync(0xffffffffu, mx, off));
    float se = expf(l[0] - mx) + expf(l[1] - mx) + expf(l[2] - mx) + expf(l[3] - mx);
    #pragma unroll
    for (int off = 16; off; off >>= 1) se += __shfl_xor_sync(0xffffffffu, se, off);
    float lossv = 0.f;
    if (lane == 0) {
        int lab = y[row];
        float ll = g_logits[(size_t)row * CC + lab] + b[lab];
        lossv = (mx + logf(se) - ll) * (1.0f / NN);
    }

    #pragma unroll
    for (int off = 16; off; off >>= 1) {
        float r0 = __shfl_down_sync(0xffffffffu, t0, off);
        float r1 = __shfl_down_sync(0xffffffffu, t1, off);
        float r2 = __shfl_down_sync(0xffffffffu, t2, off);
        ins3f(t0, t1, t2, r0); ins3f(t0, t1, t2, r1); ins3f(t0, t1, t2, r2);
    }
    unsigned b0 = __shfl_sync(0xffffffffu, __float_as_uint(t0), 0);
    unsigned b1 = __shfl_sync(0xffffffffu, __float_as_uint(t1), 0);
    unsigned b2 = __shfl_sync(0xffffffffu, __float_as_uint(t2), 0);

    int yi = y[row];
    float acc = 0.f;
    #pragma unroll
    for (int tq = 0; tq < 3; ++tq) {
        unsigned bt = (tq == 0) ? b0 : (tq == 1) ? b1 : b2;
        int n = (int)(bt & 0xFFFu);
        float e2;
        bool use = true;
        if      (n == 0) e2 = __uint_as_float(b0 & 0xFFFFF000u);
        else if (n == 1) e2 = __uint_as_float(b1 & 0xFFFFF000u);
        else if (n == 2) e2 = __uint_as_float(b2 & 0xFFFFF000u);
        else { e2 = 0.f; use = false; }  // exp(-d_sorted[i, n>=3]) <= ~2e-12: drop
        if (!use) continue;
        if (y[n] != yi) continue;
        float s = 0.f;
        #pragma unroll
        for (int q = 0; q < 4; ++q) {
            float dv = yo[(size_t)row * CC + lane + 32 * q] - yo[(size_t)n * CC + lane + 32 * q];
            s = fmaf(dv, dv, s);
        }
        #pragma unroll
        for (int off = 16; off; off >>= 1) s += __shfl_xor_sync(0xffffffffu, s, off);
        acc += sqrtf(s) * expf(-sqrtf(e2));
    }

    if (lane == 0) { s_loss[w] = lossv; s_reg[w] = acc; }
    __syncthreads();
    if (threadIdx.x == 0) {
        float L = 0.f, R = 0.f;
        #pragma unroll
        for (int i = 0; i < 8; ++i) { L += s_loss[i]; R += s_reg[i]; }
        atomicAdd(&g_loss, L);
        atomicAdd(&g_reg, R);
        __threadfence();
        unsigned done = atomicAdd(&g_done, 1u);
        if (done == gridDim.x - 1) {
            __threadfence();
            out[0] = *(volatile float*)&g_loss + ALPHA_ * *(volatile float*)&g_reg;
        }
    }
}

extern "C" void kernel_launch(void* const* d_in, const int* in_sizes, int n_in,
                              void* d_out, int out_size) {
    (void)in_sizes; (void)n_in; (void)out_size;
    const float* x  = (const float*)d_in[0];
    const int*   y  = (const int*)d_in[1];
    const float* yo = (const float*)d_in[2];
    const float* W  = (const float*)d_in[3];
    const float* b  = (const float*)d_in[4];
    float* out = (float*)d_out;

    const int DYN_FUSED = 4 * 18432;          // 73728 >= 62464 (distance path)
    cudaFuncSetAttribute(k_gemm_fused, cudaFuncAttributeMaxDynamicSharedMemorySize, DYN_FUSED);

    k_cvt_sq<<<768, 256>>>(x, W);
    k_gemm_fused<<<NBLK_DIST + 128, 256, DYN_FUSED>>>();
    k_tail<<<NN / 8, 256>>>(y, yo, b, out);
}

// round 17
// speedup vs baseline: 1.0223x; 1.0223x over previous
#include <cuda_runtime.h>
#include <cuda_bf16.h>
#include <math.h>

#define NN 4096
#define DD 512
#define CC 128
#define ALPHA_ 0.0005f
#define NT 32
#define NBLK_DIST (NT * (NT + 1) / 2)   // 528
#define NBLK_LOSS 128
#define KEY_EMPTY __uint_as_float(0x7f7fffffu)

typedef unsigned long long ull;

__device__ float g_sq[NN];
__device__ float g_part[NN * NT * 3];
__device__ float g_loss;
__device__ float g_reg;
__device__ unsigned g_done;
__device__ float g_logits[NN * CC];
__device__ __nv_bfloat16 g_xhi[NN * DD];
__device__ __nv_bfloat16 g_xlo[NN * DD];
__device__ __nv_bfloat16 g_wt_hi[CC * DD];
__device__ __nv_bfloat16 g_wt_lo[CC * DD];

__device__ __forceinline__ void ins3f(float &a0, float &a1, float &a2, float k) {
    a2 = fminf(a2, k);
    float lo = fminf(a1, a2), hi = fmaxf(a1, a2);
    a1 = lo; a2 = hi;
    lo = fminf(a0, a1); hi = fmaxf(a0, a1);
    a0 = lo; a1 = hi;
}

__device__ __forceinline__ float packkey(float e2, unsigned idx) {
    return __uint_as_float((__float_as_uint(e2) & 0xFFFFF000u) | idx);
}

__device__ __forceinline__ unsigned smem_u32(const void* p) {
    unsigned a;
    asm("{ .reg .u64 t; cvta.to.shared.u64 t, %1; cvt.u32.u64 %0, t; }" : "=r"(a) : "l"(p));
    return a;
}

#define LDSMX4(r0, r1, r2, r3, addr) \
    asm volatile("ldmatrix.sync.aligned.m8n8.x4.shared.b16 {%0,%1,%2,%3}, [%4];" \
        : "=r"(r0), "=r"(r1), "=r"(r2), "=r"(r3) : "r"(addr))

#define MMA16816(d, a, b) \
    asm volatile("mma.sync.aligned.m16n8k16.row.col.f32.bf16.bf16.f32 " \
        "{%0,%1,%2,%3}, {%4,%5,%6,%7}, {%8,%9}, {%0,%1,%2,%3};" \
        : "+f"((d)[0]), "+f"((d)[1]), "+f"((d)[2]), "+f"((d)[3]) \
        : "r"((a)[0]), "r"((a)[1]), "r"((a)[2]), "r"((a)[3]), "r"((b)[0]), "r"((b)[1]))

// blocks 0..255: bf16 hi/lo split + sq-norms, 2 rows/warp (MLP 8)
// blocks 256..511: W^T prep + logits zero + init
__global__ void k_cvt_sq(const float* __restrict__ x, const float* __restrict__ W) {
    if (blockIdx.x >= 256) {
        int idx = (blockIdx.x - 256) * 256 + threadIdx.x;   // 0..65535
        if (idx == 0) { g_loss = 0.f; g_reg = 0.f; g_done = 0u; }
        int c = idx >> 9, d = idx & 511;
        float v = W[d * CC + c];
        __nv_bfloat16 h = __float2bfloat16(v);
        __nv_bfloat16 l = __float2bfloat16(v - __bfloat162float(h));
        g_wt_hi[c * DD + d] = h;
        g_wt_lo[c * DD + d] = l;
        float4 z = make_float4(0.f, 0.f, 0.f, 0.f);
        ((float4*)g_logits)[idx] = z;
        ((float4*)g_logits)[idx + 65536] = z;
        return;
    }
    int warpId = (blockIdx.x * 256 + threadIdx.x) >> 5;     // 0..2047
    int lane   = threadIdx.x & 31;
    int row0   = warpId * 2;

    // issue all 8 loads before any dependent math
    float4 v[2][4];
    #pragma unroll
    for (int r = 0; r < 2; ++r)
        #pragma unroll
        for (int q = 0; q < 4; ++q)
            v[r][q] = *(const float4*)(x + (size_t)(row0 + r) * DD + lane * 4 + q * 128);

    #pragma unroll
    for (int r = 0; r < 2; ++r) {
        float s = 0.f;
        #pragma unroll
        for (int q = 0; q < 4; ++q) {
            float4 w = v[r][q];
            s = fmaf(w.x, w.x, s); s = fmaf(w.y, w.y, s);
            s = fmaf(w.z, w.z, s); s = fmaf(w.w, w.w, s);
            __nv_bfloat16 h0 = __float2bfloat16(w.x), h1 = __float2bfloat16(w.y);
            __nv_bfloat16 h2 = __float2bfloat16(w.z), h3 = __float2bfloat16(w.w);
            __nv_bfloat16 l0 = __float2bfloat16(w.x - __bfloat162float(h0));
            __nv_bfloat16 l1 = __float2bfloat16(w.y - __bfloat162float(h1));
            __nv_bfloat16 l2 = __float2bfloat16(w.z - __bfloat162float(h2));
            __nv_bfloat16 l3 = __float2bfloat16(w.w - __bfloat162float(h3));
            size_t i = (size_t)(row0 + r) * DD + lane * 4 + q * 128;
            __nv_bfloat162 hA; hA.x = h0; hA.y = h1;
            __nv_bfloat162 hB; hB.x = h2; hB.y = h3;
            __nv_bfloat162 lA; lA.x = l0; lA.y = l1;
            __nv_bfloat162 lB; lB.x = l2; lB.y = l3;
            *(__nv_bfloat162*)(g_xhi + i)     = hA;
            *(__nv_bfloat162*)(g_xhi + i + 2) = hB;
            *(__nv_bfloat162*)(g_xlo + i)     = lA;
            *(__nv_bfloat162*)(g_xlo + i + 2) = lB;
        }
        #pragma unroll
        for (int off = 16; off; off >>= 1) s += __shfl_down_sync(0xffffffffu, s, off);
        if (lane == 0) g_sq[row0 + r] = s;
    }
}

// ---- loss-GEMM path (blocks < NBLK_LOSS of the fused kernel) ----
__device__ void loss_mma_body(char* dsm, int bid) {
    const unsigned TILESZ = 18432;
    int t = threadIdx.x, lane = t & 31, wid = t >> 5;
    int wm = wid >> 1, wn = wid & 1;
    int mbase = wm * 32, nbase = wn * 64;

    int rg = bid >> 2;
    int ks = bid & 3;
    int rowA = rg * 128;
    int dbase = ks * 128;

    unsigned sb = smem_u32(dsm);
    unsigned aOff = (mbase + (lane & 15)) * 144 + (lane >> 4) * 16;
    unsigned bOff = (nbase + (lane & 7) + ((lane >> 4) << 3)) * 144 + ((lane >> 3) & 1) * 16;

    float acc[2][8][4];
    #pragma unroll
    for (int i = 0; i < 2; i++)
        #pragma unroll
        for (int j = 0; j < 8; j++)
            #pragma unroll
            for (int k = 0; k < 4; k++) acc[i][j][k] = 0.f;

    for (int chunk = 0; chunk < 2; ++chunk) {
        int d0 = dbase + chunk * 64;
        __syncthreads();
        #pragma unroll
        for (int it = 0; it < 16; ++it) {
            int i = t + 256 * it;
            int tile = i >> 10, rem = i & 1023;
            int r = rem >> 3, q = rem & 7;
            const __nv_bfloat16* src;
            if      (tile == 0) src = g_xhi  + (size_t)(rowA + r) * DD + d0 + q * 8;
            else if (tile == 1) src = g_xlo  + (size_t)(rowA + r) * DD + d0 + q * 8;
            else if (tile == 2) src = g_wt_hi + (size_t)r * DD + d0 + q * 8;
            else                src = g_wt_lo + (size_t)r * DD + d0 + q * 8;
            *(float4*)(dsm + tile * TILESZ + r * 144 + q * 16) = *(const float4*)src;
        }
        __syncthreads();

        unsigned baseAh = sb, baseAl = sb + TILESZ, baseBh = sb + 2 * TILESZ, baseBl = sb + 3 * TILESZ;
        #pragma unroll
        for (int kh = 0; kh < 4; ++kh) {
            unsigned ko = kh * 32;
            unsigned aH[2][4], aL[2][4], bH[8][2], bL[8][2];
            LDSMX4(aH[0][0], aH[0][1], aH[0][2], aH[0][3], baseAh + aOff + ko);
            LDSMX4(aH[1][0], aH[1][1], aH[1][2], aH[1][3], baseAh + aOff + 16 * 144 + ko);
            LDSMX4(aL[0][0], aL[0][1], aL[0][2], aL[0][3], baseAl + aOff + ko);
            LDSMX4(aL[1][0], aL[1][1], aL[1][2], aL[1][3], baseAl + aOff + 16 * 144 + ko);
            #pragma unroll
            for (int g = 0; g < 4; ++g) {
                LDSMX4(bH[2*g][0], bH[2*g][1], bH[2*g+1][0], bH[2*g+1][1],
                       baseBh + bOff + g * 16 * 144 + ko);
                LDSMX4(bL[2*g][0], bL[2*g][1], bL[2*g+1][0], bL[2*g+1][1],
                       baseBl + bOff + g * 16 * 144 + ko);
            }
            #pragma unroll
            for (int mt = 0; mt < 2; ++mt)
                #pragma unroll
                for (int nt = 0; nt < 8; ++nt) {
                    MMA16816(acc[mt][nt], aH[mt], bH[nt]);
                    MMA16816(acc[mt][nt], aH[mt], bL[nt]);
                    MMA16816(acc[mt][nt], aL[mt], bH[nt]);
                }
        }
    }

    #pragma unroll
    for (int mt = 0; mt < 2; ++mt)
        #pragma unroll
        for (int nt = 0; nt < 8; ++nt)
            #pragma unroll
            for (int c4 = 0; c4 < 4; ++c4) {
                int h = c4 >> 1, c = c4 & 1;
                int ml = mbase + mt * 16 + (lane >> 2) + h * 8;
                int nl = nbase + nt * 8 + 2 * (lane & 3) + c;
                atomicAdd(&g_logits[(size_t)(rowA + ml) * CC + nl], acc[mt][nt][c4]);
            }
}

// ---- fused GEMM kernel: blocks [0,128) loss logits (short, frees slots early),
// ----                    blocks [128,656) distance+top3
__global__ __launch_bounds__(256, 2) void k_gemm_fused() {
    extern __shared__ __align__(16) char dsm[];

    if (blockIdx.x < NBLK_LOSS) {
        loss_mma_body(dsm, blockIdx.x);
        return;
    }

    float* s_sqA = (float*)dsm;
    float* s_sqB = (float*)(dsm + 512);
    const unsigned BUF0 = 1024, BUFSZ = 20480, TILESZ = 10240;

    int t = threadIdx.x, lane = t & 31, wid = t >> 5;
    int wm = wid >> 1, wn = wid & 1;
    int mbase = wm * 32, nbase = wn * 64;

    int id = blockIdx.x - NBLK_LOSS, by = 0;
    while (id >= NT - by) { id -= NT - by; by++; }
    int bx = by + id;
    int rowA = by * 128, rowB = bx * 128;

    if (t < 128) { s_sqA[t] = g_sq[rowA + t]; s_sqB[t] = g_sq[rowB + t]; }

    unsigned sb = smem_u32(dsm);

    const char* srcPtr[4];
    unsigned dstOff[4];
    #pragma unroll
    for (int c = 0; c < 4; ++c) {
        int tile = c & 1, part = c >> 1;
        int i2 = t + 256 * part;
        int r = i2 >> 2, q = i2 & 3;
        int rowT = tile ? rowB : rowA;
        srcPtr[c] = (const char*)g_xhi + ((size_t)(rowT + r) << 10) + q * 16;
        dstOff[c] = BUF0 + tile * TILESZ + r * 80 + q * 16;
    }

    float acc[2][8][4];
    #pragma unroll
    for (int i = 0; i < 2; i++)
        #pragma unroll
        for (int j = 0; j < 8; j++)
            #pragma unroll
            for (int k = 0; k < 4; k++) acc[i][j][k] = 0.f;

    unsigned aOff = ((mbase + (lane & 15)) * 40 + (lane >> 4) * 8) * 2;
    unsigned bOff = ((nbase + (lane & 7) + ((lane >> 4) << 3)) * 40 + ((lane >> 3) & 1) * 8) * 2;

    #pragma unroll
    for (int c = 0; c < 4; ++c)
        asm volatile("cp.async.cg.shared.global [%0], [%1], 16;"
            :: "r"(sb + dstOff[c]), "l"(srcPtr[c]) : "memory");
    asm volatile("cp.async.commit_group;" ::: "memory");
    #pragma unroll
    for (int c = 0; c < 4; ++c)
        asm volatile("cp.async.cg.shared.global [%0], [%1], 16;"
            :: "r"(sb + dstOff[c] + BUFSZ), "l"(srcPtr[c] + 64) : "memory");
    asm volatile("cp.async.commit_group;" ::: "memory");

    for (int s = 0; s < 16; ++s) {
        if (s < 15) asm volatile("cp.async.wait_group 1;" ::: "memory");
        else        asm volatile("cp.async.wait_group 0;" ::: "memory");
        __syncthreads();

        if (s + 2 < 16) {
            unsigned bofs = ((s + 2) % 3) * BUFSZ;
            #pragma unroll
            for (int c = 0; c < 4; ++c)
                asm volatile("cp.async.cg.shared.global [%0], [%1], 16;"
                    :: "r"(sb + dstOff[c] + bofs), "l"(srcPtr[c] + (size_t)(s + 2) * 64) : "memory");
            asm volatile("cp.async.commit_group;" ::: "memory");
        }

        unsigned bb = sb + BUF0 + (s % 3) * BUFSZ;
        unsigned baseA = bb, baseB = bb + TILESZ;

        #pragma unroll
        for (int kh = 0; kh < 2; ++kh) {
            unsigned ko = kh * 32;
            unsigned aH[2][4], bb2[8][2];
            LDSMX4(aH[0][0], aH[0][1], aH[0][2], aH[0][3], baseA + aOff + ko);
            LDSMX4(aH[1][0], aH[1][1], aH[1][2], aH[1][3], baseA + aOff + 16 * 80 + ko);
            #pragma unroll
            for (int g = 0; g < 4; ++g)
                LDSMX4(bb2[2*g][0], bb2[2*g][1], bb2[2*g+1][0], bb2[2*g+1][1],
                       baseB + bOff + g * 16 * 80 + ko);
            #pragma unroll
            for (int mt = 0; mt < 2; ++mt)
                #pragma unroll
                for (int nt = 0; nt < 8; ++nt)
                    MMA16816(acc[mt][nt], aH[mt], bb2[nt]);
        }
    }
    __syncthreads();

    const float* sqa = s_sqA;
    const float* sqb = s_sqB;
    #pragma unroll
    for (int mt = 0; mt < 2; ++mt)
        #pragma unroll
        for (int nt = 0; nt < 8; ++nt)
            #pragma unroll
            for (int c4 = 0; c4 < 4; ++c4) {
                int h = c4 >> 1, c = c4 & 1;
                int ml = mbase + mt * 16 + (lane >> 2) + h * 8;
                int nl = nbase + nt * 8 + 2 * (lane & 3) + c;
                float d2 = sqa[ml] + sqb[nl] - 2.f * acc[mt][nt][c4];
                float e2 = d2 > 0.f ? d2 : 0.f;
                if (rowA + ml == rowB + nl) e2 = 0.f;
                acc[mt][nt][c4] = e2;
            }

    float* p_r = (float*)(dsm + BUF0);
    float* p_c = (float*)(dsm + BUF0 + 4096);

    #pragma unroll
    for (int mt = 0; mt < 2; ++mt)
        #pragma unroll
        for (int h = 0; h < 2; ++h) {
            int ml = mbase + mt * 16 + (lane >> 2) + h * 8;
            float t0 = KEY_EMPTY, t1 = KEY_EMPTY, t2 = KEY_EMPTY;
            #pragma unroll
            for (int nt = 0; nt < 8; ++nt)
                #pragma unroll
                for (int c = 0; c < 2; ++c) {
                    int nl = nbase + nt * 8 + 2 * (lane & 3) + c;
                    ins3f(t0, t1, t2, packkey(acc[mt][nt][2 * h + c], (unsigned)(rowB + nl)));
                }
            #pragma unroll
            for (int off = 1; off <= 2; off <<= 1) {
                float r0 = __shfl_xor_sync(0xffffffffu, t0, off);
                float r1 = __shfl_xor_sync(0xffffffffu, t1, off);
                float r2 = __shfl_xor_sync(0xffffffffu, t2, off);
                ins3f(t0, t1, t2, r0); ins3f(t0, t1, t2, r1); ins3f(t0, t1, t2, r2);
            }
            if ((lane & 3) == 0) {
                int b = (ml * 2 + wn) * 3;
                p_r[b + 0] = t0; p_r[b + 1] = t1; p_r[b + 2] = t2;
            }
        }

    if (bx != by) {
        #pragma unroll
        for (int nt = 0; nt < 8; ++nt)
            #pragma unroll
            for (int c = 0; c < 2; ++c) {
                int nl = nbase + nt * 8 + 2 * (lane & 3) + c;
                float t0 = KEY_EMPTY, t1 = KEY_EMPTY, t2 = KEY_EMPTY;
                #pragma unroll
                for (int mt = 0; mt < 2; ++mt)
                    #pragma unroll
                    for (int h = 0; h < 2; ++h) {
                        int ml = mbase + mt * 16 + (lane >> 2) + h * 8;
                        ins3f(t0, t1, t2, packkey(acc[mt][nt][2 * h + c], (unsigned)(rowA + ml)));
                    }
                #pragma unroll
                for (int off = 4; off <= 16; off <<= 1) {
                    float r0 = __shfl_xor_sync(0xffffffffu, t0, off);
                    float r1 = __shfl_xor_sync(0xffffffffu, t1, off);
                    float r2 = __shfl_xor_sync(0xffffffffu, t2, off);
                    ins3f(t0, t1, t2, r0); ins3f(t0, t1, t2, r1); ins3f(t0, t1, t2, r2);
                }
                if (lane < 4) {
                    int b = (nl * 4 + wm) * 3;
                    p_c[b + 0] = t0; p_c[b + 1] = t1; p_c[b + 2] = t2;
                }
            }
    }

    __syncthreads();
    if (t < 128) {
        float t0 = KEY_EMPTY, t1 = KEY_EMPTY, t2 = KEY_EMPTY;
        #pragma unroll
        for (int g = 0; g < 6; ++g) ins3f(t0, t1, t2, p_r[t * 6 + g]);
        size_t base = ((size_t)(rowA + t) * NT + bx) * 3;
        g_part[base + 0] = t0; g_part[base + 1] = t1; g_part[base + 2] = t2;
    } else if (bx != by) {
        int n = t - 128;
        float t0 = KEY_EMPTY, t1 = KEY_EMPTY, t2 = KEY_EMPTY;
        #pragma unroll
        for (int g = 0; g < 12; ++g) ins3f(t0, t1, t2, p_c[n * 12 + g]);
        size_t base = ((size_t)(rowB + n) * NT + by) * 3;
        g_part[base + 0] = t0; g_part[base + 1] = t1; g_part[base + 2] = t2;
    }
}

// fused: softmax+NLL and merge+reg, warp per row; block-reduced atomics; last block writes out
__global__ void k_tail(const int* __restrict__ y, const float* __restrict__ yo,
                       const float* __restrict__ b, float* __restrict__ out) {
    __shared__ float s_loss[8];
    __shared__ float s_reg[8];
    int w    = threadIdx.x >> 5;
    int row  = blockIdx.x * 8 + w;
    int lane = threadIdx.x & 31;

    float l[4];
    #pragma unroll
    for (int q = 0; q < 4; ++q)
        l[q] = g_logits[(size_t)row * CC + lane + 32 * q] + b[lane + 32 * q];
    float t0 = KEY_EMPTY, t1 = KEY_EMPTY, t2 = KEY_EMPTY;
    size_t pbase = (size_t)row * (NT * 3);
    #pragma unroll
    for (int p = 0; p < 3; ++p) ins3f(t0, t1, t2, g_part[pbase + lane + 32 * p]);

    float mx = fmaxf(fmaxf(l[0], l[1]), fmaxf(l[2], l[3]));
    #pragma unroll
    for (int off = 16; off; off >>= 1) mx = fmaxf(mx, __shfl_xor_sync(0xffffffffu, mx, off));
    float se = expf(l[0] - mx) + expf(l[1] - mx) + expf(l[2] - mx) + expf(l[3] - mx);
    #pragma unroll
    for (int off = 16; off; off >>= 1) se += __shfl_xor_sync(0xffffffffu, se, off);
    float lossv = 0.f;
    if (lane == 0) {
        int lab = y[row];
        float ll = g_logits[(size_t)row * CC + lab] + b[lab];
        lossv = (mx + logf(se) - ll) * (1.0f / NN);
    }

    #pragma unroll
    for (int off = 16; off; off >>= 1) {
        float r0 = __shfl_down_sync(0xffffffffu, t0, off);
        float r1 = __shfl_down_sync(0xffffffffu, t1, off);
        float r2 = __shfl_down_sync(0xffffffffu, t2, off);
        ins3f(t0, t1, t2, r0); ins3f(t0, t1, t2, r1); ins3f(t0, t1, t2, r2);
    }
    unsigned b0 = __shfl_sync(0xffffffffu, __float_as_uint(t0), 0);
    unsigned b1 = __shfl_sync(0xffffffffu, __float_as_uint(t1), 0);
    unsigned b2 = __shfl_sync(0xffffffffu, __float_as_uint(t2), 0);

    int yi = y[row];
    float acc = 0.f;
    #pragma unroll
    for (int tq = 0; tq < 3; ++tq) {
        unsigned bt = (tq == 0) ? b0 : (tq == 1) ? b1 : b2;
        int n = (int)(bt & 0xFFFu);
        float e2;
        bool use = true;
        if      (n == 0) e2 = __uint_as_float(b0 & 0xFFFFF000u);
        else if (n == 1) e2 = __uint_as_float(b1 & 0xFFFFF000u);
        else if (n == 2) e2 = __uint_as_float(b2 & 0xFFFFF000u);
        else { e2 = 0.f; use = false; }  // exp(-d_sorted[i, n>=3]) <= ~2e-12: drop
        if (!use) continue;
        if (y[n] != yi) continue;
        float s = 0.f;
        #pragma unroll
        for (int q = 0; q < 4; ++q) {
            float dv = yo[(size_t)row * CC + lane + 32 * q] - yo[(size_t)n * CC + lane + 32 * q];
            s = fmaf(dv, dv, s);
        }
        #pragma unroll
        for (int off = 16; off; off >>= 1) s += __shfl_xor_sync(0xffffffffu, s, off);
        acc += sqrtf(s) * expf(-sqrtf(e2));
    }

    if (lane == 0) { s_loss[w] = lossv; s_reg[w] = acc; }
    __syncthreads();
    if (threadIdx.x == 0) {
        float L = 0.f, R = 0.f;
        #pragma unroll
        for (int i = 0; i < 8; ++i) { L += s_loss[i]; R += s_reg[i]; }
        atomicAdd(&g_loss, L);
        atomicAdd(&g_reg, R);
        __threadfence();
        unsigned done = atomicAdd(&g_done, 1u);
        if (done == gridDim.x - 1) {
            __threadfence();
            out[0] = *(volatile float*)&g_loss + ALPHA_ * *(volatile float*)&g_reg;
        }
    }
}

extern "C" void kernel_launch(void* const* d_in, const int* in_sizes, int n_in,
                              void* d_out, int out_size) {
    (void)in_sizes; (void)n_in; (void)out_size;
    const float* x  = (const float*)d_in[0];
    const int*   y  = (const int*)d_in[1];
    const float* yo = (const float*)d_in[2];
    const float* W  = (const float*)d_in[3];
    const float* b  = (const float*)d_in[4];
    float* out = (float*)d_out;

    const int DYN_FUSED = 4 * 18432;          // 73728 >= 62464 (distance path)
    cudaFuncSetAttribute(k_gemm_fused, cudaFuncAttributeMaxDynamicSharedMemorySize, DYN_FUSED);

    k_cvt_sq<<<512, 256>>>(x, W);
    k_gemm_fused<<<NBLK_LOSS + NBLK_DIST, 256, DYN_FUSED>>>();
    k_tail<<<NN / 8, 256>>>(y, yo, b, out);
}